// round 15
// baseline (speedup 1.0000x reference)
#include <cuda_runtime.h>
#include <cuda_fp16.h>
#include <cstddef>
#include <cstdint>

// ---------------- problem constants ----------------
#define MAXN   20000
#define NN     32
#define INF    256
#define MID    128
#define OUTF   512
#define NKP    15
#define KPAD   16
#define KWF    (MID * KPAD)   // 2048: wf K-dim, [c][k] layout, k padded to 16
#define EXTENT 0.5f
#define INV_EXTENT 2.0f

// ---------------- scratch (allocation-free) ----------------
__device__ __half g_xh  [(size_t)MAXN * MID];      // conv1 output (fp16)
__device__ __half g_wfh [(size_t)MAXN * KWF];      // wf / wf2 (fp16, [c][k16])
__device__ float  g_dkp [(size_t)MAXN * NKP*3];    // deformed KPs (fp32)
__device__ __half g_yh  [(size_t)MAXN * MID];      // conv2 output (fp16)
__device__ __half g_feath[(size_t)MAXN * INF];     // features (fp16)
// fp16 K-major weights: Wst | W3t | Kvt | w0t
#define OFF_WSTH 0
#define OFF_W3TH (OFF_WSTH + 512*256)
#define OFF_KVTH (OFF_W3TH + 512*128)
#define OFF_W0TH (OFF_KVTH + 128*KWF)
#define WTH_TOTAL (OFF_W0TH + 64*KWF)
__device__ __half g_wth[WTH_TOTAL];

__device__ __forceinline__ float lrelu(float x) { return fmaxf(x, 0.1f * x); }
__device__ __forceinline__ void fma2(float2 &d, float2 a, float2 b) {
    asm("fma.rn.f32x2 %0, %1, %2, %0;"
        : "+l"(reinterpret_cast<unsigned long long&>(d))
        : "l"(reinterpret_cast<unsigned long long&>(a)),
          "l"(reinterpret_cast<unsigned long long&>(b)));
}
__device__ __forceinline__ uint32_t smem_u32(const void* p) {
    uint32_t a;
    asm("{ .reg .u64 t; cvta.to.shared.u64 t, %1; cvt.u32.u64 %0, t; }" : "=r"(a) : "l"(p));
    return a;
}
__device__ __forceinline__ void cpasync16(uint32_t dst, const void* src, bool pred) {
    int sz = pred ? 16 : 0;
    asm volatile("cp.async.cg.shared.global [%0], [%1], 16, %2;"
                 :: "r"(dst), "l"(src), "r"(sz));
}
#define CP_COMMIT() asm volatile("cp.async.commit_group;")
#define CP_WAIT(n)  asm volatile("cp.async.wait_group %0;" :: "n"(n))

__device__ __forceinline__ void mma_f16(float* d, const uint32_t* a, const uint32_t* b) {
    asm volatile(
        "mma.sync.aligned.m16n8k16.row.col.f32.f16.f16.f32 "
        "{%0,%1,%2,%3}, {%4,%5,%6,%7}, {%8,%9}, {%0,%1,%2,%3};"
        : "+f"(d[0]), "+f"(d[1]), "+f"(d[2]), "+f"(d[3])
        : "r"(a[0]), "r"(a[1]), "r"(a[2]), "r"(a[3]), "r"(b[0]), "r"(b[1]));
}

// =====================================================================
// Merged prep: features->fp16 + weight transposes. One launch.
// Kv/w0 go to [o][c*16+k] layout (k padded to 16 with zeros).
// =====================================================================
__global__ void prep_kernel(const float* __restrict__ feat,
                            const float* __restrict__ Ws, const float* __restrict__ W3,
                            const float* __restrict__ Kv, const float* __restrict__ w0,
                            __half* __restrict__ pfth, __half* __restrict__ pwth, int nfeat)
{
    int idx = blockIdx.x * 256 + threadIdx.x;
    if (idx < nfeat) { pfth[idx] = __float2half_rn(feat[idx]); return; }
    idx -= nfeat;
    if (idx < 512 * 256) {                      // Wst [512,256] <- Ws[256,512]
        int nr = idx >> 8, k = idx & 255;
        pwth[OFF_WSTH + idx] = __float2half_rn(Ws[(size_t)k * 512 + nr]);
        return;
    }
    idx -= 512 * 256;
    if (idx < 512 * 128) {                      // W3t [512,128] <- W3[128,512]
        int nr = idx >> 7, k = idx & 127;
        pwth[OFF_W3TH + idx] = __float2half_rn(W3[(size_t)k * 512 + nr]);
        return;
    }
    idx -= 512 * 128;
    if (idx < 128 * KWF) {                      // Kvt [128][c*16+k] <- Kv[k,c,o]
        int o = idx / KWF, r = idx - o * KWF;
        int c = r >> 4, k = r & 15;
        pwth[OFF_KVTH + idx] = (k < NKP)
            ? __float2half_rn(Kv[((size_t)k * 128 + c) * 128 + o])
            : __float2half_rn(0.0f);
        return;
    }
    idx -= 128 * KWF;
    if (idx < 64 * KWF) {                       // w0t [64][c*16+k] <- w0[k,c,o]
        int o = idx / KWF, r = idx - o * KWF;
        int c = r >> 4, k = r & 15;
        pwth[OFF_W0TH + idx] = (k < NKP && o < 45)
            ? __float2half_rn(w0[((size_t)k * 128 + c) * 45 + o])
            : __float2half_rn(0.0f);
    }
}
#define PREP_EXTRA (512*256 + 512*128 + 128*KWF + 64*KWF)

// =====================================================================
// Exact fp32 SGEMM (f32x2): C(half) = lrelu(A @ B). Used for conv1.
// =====================================================================
__global__ __launch_bounds__(256)
void fp32_gemm(const float* __restrict__ A, const float* __restrict__ B,
               __half* __restrict__ C, int M, int N, int K)
{
    constexpr int BM = 128, BN = 128, BK = 16;
    __shared__ float As[BK][BM];
    __shared__ float Bs[BK][BN];

    const int tid  = threadIdx.x;
    const int bm   = blockIdx.y * BM;
    const int bn   = blockIdx.x * BN;
    const int trow = (tid / 16) * 8;
    const int tcol = (tid % 16) * 8;

    float2 acc[8][4];
#pragma unroll
    for (int m = 0; m < 8; m++)
#pragma unroll
        for (int j = 0; j < 4; j++) acc[m][j] = make_float2(0.f, 0.f);

    for (int k0 = 0; k0 < K; k0 += BK) {
#pragma unroll
        for (int i = 0; i < 2; i++) {
            int idx = tid + i * 256;
            int r = idx >> 2;
            int c = (idx & 3) << 2;
            float4 v = make_float4(0.f, 0.f, 0.f, 0.f);
            if (bm + r < M)
                v = *(const float4*)(A + (size_t)(bm + r) * K + k0 + c);
            As[c + 0][r] = v.x; As[c + 1][r] = v.y;
            As[c + 2][r] = v.z; As[c + 3][r] = v.w;
        }
#pragma unroll
        for (int i = 0; i < 2; i++) {
            int idx = tid + i * 256;
            int r = idx >> 5;
            int c = (idx & 31) << 2;
            *(float4*)&Bs[r][c] = *(const float4*)(B + (size_t)(k0 + r) * N + bn + c);
        }
        __syncthreads();

#pragma unroll
        for (int kk = 0; kk < BK; kk++) {
            float a[8];
            float2 b[4];
            {
                float4 t0 = *(const float4*)&As[kk][trow];
                float4 t1 = *(const float4*)&As[kk][trow + 4];
                a[0]=t0.x; a[1]=t0.y; a[2]=t0.z; a[3]=t0.w;
                a[4]=t1.x; a[5]=t1.y; a[6]=t1.z; a[7]=t1.w;
            }
#pragma unroll
            for (int j = 0; j < 4; j++) b[j] = *(const float2*)&Bs[kk][tcol + 2 * j];
#pragma unroll
            for (int m = 0; m < 8; m++) {
                float2 am = make_float2(a[m], a[m]);
#pragma unroll
                for (int j = 0; j < 4; j++) fma2(acc[m][j], am, b[j]);
            }
        }
        __syncthreads();
    }

#pragma unroll
    for (int m = 0; m < 8; m++) {
        int row = bm + trow + m;
        if (row >= M) continue;
        __half2 h[4];
#pragma unroll
        for (int j = 0; j < 4; j++)
            h[j] = __floats2half2_rn(lrelu(acc[m][j].x), lrelu(acc[m][j].y));
        *(uint2*)(C + (size_t)row * N + bn + tcol) =
            make_uint2(*(uint32_t*)&h[0], *(uint32_t*)&h[1]);
        *(uint2*)(C + (size_t)row * N + bn + tcol + 4) =
            make_uint2(*(uint32_t*)&h[2], *(uint32_t*)&h[3]);
    }
}

// =====================================================================
// FP16 mma.sync GEMM (m16n8k16, fp32 accumulate). BK=64 halves.
// NW=4 when BM==32 (warp tiles 16xWN) else (BN==128?4:2).
// MODE 0: Cf = lrelu(acc)                          (shortcut, float out)
// MODE 1: Cf = lrelu(lrelu(acc) + Cf)              (conv3 residual, float)
// MODE 2: dkp[i,o<45] = KP[o] + (acc+b0[o])*EXTENT (f0)
// MODE 3: Ch = half(lrelu(acc))                    (conv2 -> y fp16)
// =====================================================================
template<int BM, int BN, int MODE>
__global__ __launch_bounds__(256)
void mma_gemm_f16(const __half* __restrict__ A, const __half* __restrict__ Bt,
                  void* __restrict__ Cv, const float* __restrict__ b0,
                  const float* __restrict__ KP, int M, int K, int Nf)
{
    constexpr int BK = 64;
    constexpr int NW = (BM == 32) ? 4 : ((BN == 128) ? 4 : 2);
    constexpr int MW = 8 / NW;
    constexpr int WM = BM / MW;
    constexpr int WN = BN / NW;
    constexpr int AM = WM / 16;
    constexpr int AN = WN / 8;
    constexpr int LDS_PAD = 72;
    constexpr int ASZ = BM * LDS_PAD;
    constexpr int BSZ = BN * LDS_PAD;
    constexpr int CPR = BK / 8;

    extern __shared__ __align__(16) __half smh[];
    __half* As = smh;
    __half* Bs = smh + 2 * ASZ;
    const uint32_t sA = smem_u32(As);
    const uint32_t sB = smem_u32(Bs);

    const int tid  = threadIdx.x;
    const int lane = tid & 31;
    const int g    = lane >> 2;
    const int tig  = lane & 3;
    const int warp = tid >> 5;
    const int wm   = warp / NW;
    const int wn   = warp % NW;
    const int bm   = blockIdx.y * BM;
    const int bn   = blockIdx.x * BN;

    float acc[AM][AN][4];
#pragma unroll
    for (int i = 0; i < AM; i++)
#pragma unroll
        for (int j = 0; j < AN; j++)
#pragma unroll
            for (int e = 0; e < 4; e++) acc[i][j][e] = 0.f;

    const int NT = K / BK;

    auto load_tile = [&](int it, int buf) {
        const int k0 = it * BK;
#pragma unroll
        for (int i = 0; i < BM * CPR / 256; i++) {
            int idx = tid + i * 256;
            int r = idx / CPR, c8 = (idx % CPR) << 3;
            bool p = (bm + r) < M;
            const __half* src = A + (size_t)(p ? bm + r : 0) * K + k0 + c8;
            cpasync16(sA + (buf * ASZ + r * LDS_PAD + c8) * 2, src, p);
        }
#pragma unroll
        for (int i = 0; i < BN * CPR / 256; i++) {
            int idx = tid + i * 256;
            int r = idx / CPR, c8 = (idx % CPR) << 3;
            const __half* src = Bt + (size_t)(bn + r) * K + k0 + c8;
            cpasync16(sB + (buf * BSZ + r * LDS_PAD + c8) * 2, src, true);
        }
        CP_COMMIT();
    };

    load_tile(0, 0);
    for (int it = 0; it < NT; it++) {
        const int cur = it & 1;
        if (it + 1 < NT) { load_tile(it + 1, cur ^ 1); CP_WAIT(1); }
        else             { CP_WAIT(0); }
        __syncthreads();

        const __half* Ab = As + cur * ASZ;
        const __half* Bb = Bs + cur * BSZ;
#pragma unroll
        for (int ks = 0; ks < BK / 16; ks++) {
            const int kb = ks * 16 + 2 * tig;
            uint32_t af[AM][4], bf[AN][2];
#pragma unroll
            for (int am = 0; am < AM; am++) {
                int r0 = wm * WM + am * 16 + g;
                af[am][0] = *(const uint32_t*)&Ab[r0 * LDS_PAD + kb];
                af[am][1] = *(const uint32_t*)&Ab[(r0 + 8) * LDS_PAD + kb];
                af[am][2] = *(const uint32_t*)&Ab[r0 * LDS_PAD + kb + 8];
                af[am][3] = *(const uint32_t*)&Ab[(r0 + 8) * LDS_PAD + kb + 8];
            }
#pragma unroll
            for (int an = 0; an < AN; an++) {
                int c0 = wn * WN + an * 8 + g;
                bf[an][0] = *(const uint32_t*)&Bb[c0 * LDS_PAD + kb];
                bf[an][1] = *(const uint32_t*)&Bb[c0 * LDS_PAD + kb + 8];
            }
#pragma unroll
            for (int am = 0; am < AM; am++)
#pragma unroll
                for (int an = 0; an < AN; an++)
                    mma_f16(acc[am][an], af[am], bf[an]);
        }
        __syncthreads();
    }

    float*  Cf = (float*)Cv;
    __half* Ch = (__half*)Cv;
#pragma unroll
    for (int am = 0; am < AM; am++) {
        const int r0 = bm + wm * WM + am * 16 + g;
#pragma unroll
        for (int an = 0; an < AN; an++) {
            const int c = bn + wn * WN + an * 8 + tig * 2;
#pragma unroll
            for (int half_ = 0; half_ < 2; half_++) {
                int row = r0 + half_ * 8;
                if (row >= M) continue;
                float d0 = acc[am][an][half_ * 2 + 0];
                float d1 = acc[am][an][half_ * 2 + 1];
                if (MODE == 2) {
                    float* dp = Cf + (size_t)row * (NKP * 3);
                    if (c < NKP * 3)     dp[c]     = KP[c]     + (d0 + b0[c])     * EXTENT;
                    if (c + 1 < NKP * 3) dp[c + 1] = KP[c + 1] + (d1 + b0[c + 1]) * EXTENT;
                } else if (MODE == 3) {
                    *(__half2*)(Ch + (size_t)row * Nf + c) =
                        __floats2half2_rn(lrelu(d0), lrelu(d1));
                } else {
                    d0 = lrelu(d0); d1 = lrelu(d1);
                    float* cp = Cf + (size_t)row * Nf + c;
                    if (MODE == 1) {
                        float2 prev = *(const float2*)cp;
                        d0 = lrelu(d0 + prev.x);
                        d1 = lrelu(d1 + prev.y);
                    }
                    *(float2*)cp = make_float2(d0, d1);
                }
            }
        }
    }
}

// =====================================================================
// Per-point gather + KP-influence + weighted feature aggregation.
// 4 points per block, 256 threads, warp-uniform neighbor compaction.
// Output layout [c][k16]: each thread writes 64 contiguous bytes (4xSTG.128).
// =====================================================================
__global__ __launch_bounds__(256)
void wf_kernel(const float* __restrict__ points, const int* __restrict__ nbr,
               const __half* __restrict__ xf, const float* __restrict__ kp0,
               const float* __restrict__ dkp, __half* __restrict__ wf, int n)
{
    const int tid = threadIdx.x;
    const int i0  = blockIdx.x * 4;

    __shared__ int   s_idx[4][NN];
    __shared__ float s_w[4][NN][16];
    __shared__ int   s_cnt[4];
    __shared__ float s_ctr[4][3];

    if (tid < 12) {
        int pt = tid / 3, d = tid - pt * 3;
        int ip = i0 + pt;
        s_ctr[pt][d] = (ip < n) ? points[(size_t)ip * 3 + d] : 0.f;
    }
    __syncthreads();

    if (tid < 128) {
        const int pt = tid >> 5, j = tid & 31;
        const int ip = i0 + pt;
        int   id = 0;
        float wreg[NKP];
        bool  active = false;
        if (ip < n) {
            id = nbr[(size_t)ip * NN + j];
            float dx = points[(size_t)id * 3 + 0] - s_ctr[pt][0];
            float dy = points[(size_t)id * 3 + 1] - s_ctr[pt][1];
            float dz = points[(size_t)id * 3 + 2] - s_ctr[pt][2];
            const float* kp = dkp ? (dkp + (size_t)ip * (NKP * 3)) : kp0;
#pragma unroll
            for (int k = 0; k < NKP; k++) {
                float ex = dx - kp[k * 3 + 0];
                float ey = dy - kp[k * 3 + 1];
                float ez = dz - kp[k * 3 + 2];
                float d = sqrtf(ex * ex + ey * ey + ez * ez);
                float w = fmaxf(1.0f - d * INV_EXTENT, 0.0f);
                wreg[k] = w;
                active |= (w > 0.0f);
            }
        }
        unsigned mask = __ballot_sync(0xFFFFFFFFu, active);
        if (active) {
            int pos = __popc(mask & ((1u << j) - 1u));
            s_idx[pt][pos] = id;
#pragma unroll
            for (int k = 0; k < NKP; k++) s_w[pt][pos][k] = wreg[k];
            s_w[pt][pos][15] = 0.0f;
        }
        if (j == 0) s_cnt[pt] = __popc(mask);
    }
    __syncthreads();

    const int p  = tid >> 6;
    const int t2 = (tid & 63) << 1;
    const int i  = i0 + p;
    if (i >= n) return;
    const int cnt = s_cnt[p];

    float2 acc[NKP];
#pragma unroll
    for (int k = 0; k < NKP; k++) acc[k] = make_float2(0.f, 0.f);

#pragma unroll 4
    for (int m = 0; m < cnt; m++) {
        int id = s_idx[p][m];
        float2 f = __half22float2(*(const __half2*)(xf + (size_t)id * MID + t2));
        float4 w0_ = *(const float4*)&s_w[p][m][0];
        float4 w1_ = *(const float4*)&s_w[p][m][4];
        float4 w2_ = *(const float4*)&s_w[p][m][8];
        float4 w3_ = *(const float4*)&s_w[p][m][12];
        fma2(acc[0],  make_float2(w0_.x, w0_.x), f);
        fma2(acc[1],  make_float2(w0_.y, w0_.y), f);
        fma2(acc[2],  make_float2(w0_.z, w0_.z), f);
        fma2(acc[3],  make_float2(w0_.w, w0_.w), f);
        fma2(acc[4],  make_float2(w1_.x, w1_.x), f);
        fma2(acc[5],  make_float2(w1_.y, w1_.y), f);
        fma2(acc[6],  make_float2(w1_.z, w1_.z), f);
        fma2(acc[7],  make_float2(w1_.w, w1_.w), f);
        fma2(acc[8],  make_float2(w2_.x, w2_.x), f);
        fma2(acc[9],  make_float2(w2_.y, w2_.y), f);
        fma2(acc[10], make_float2(w2_.z, w2_.z), f);
        fma2(acc[11], make_float2(w2_.w, w2_.w), f);
        fma2(acc[12], make_float2(w3_.x, w3_.x), f);
        fma2(acc[13], make_float2(w3_.y, w3_.y), f);
        fma2(acc[14], make_float2(w3_.z, w3_.z), f);
    }

    // store [c][k16]: 32 contiguous halves (2 channels x 16 k) = 4 x 16B
    __half hbuf[32];
#pragma unroll
    for (int k = 0; k < NKP; k++) {
        hbuf[k]      = __float2half_rn(acc[k].x);
        hbuf[16 + k] = __float2half_rn(acc[k].y);
    }
    hbuf[15] = __float2half_rn(0.0f);
    hbuf[31] = __float2half_rn(0.0f);
    __half* dst = wf + (size_t)i * KWF + (size_t)t2 * KPAD;
#pragma unroll
    for (int q = 0; q < 4; q++)
        *(uint4*)(dst + q * 8) = *(uint4*)(hbuf + q * 8);
}

// =====================================================================
extern "C" void kernel_launch(void* const* d_in, const int* in_sizes, int n_in,
                              void* d_out, int out_size)
{
    const float* points   = (const float*)d_in[0];
    const float* features = (const float*)d_in[1];
    const int*   nbr      = (const int*)  d_in[2];
    const float* W1       = (const float*)d_in[3];
    const float* W3       = (const float*)d_in[4];
    const float* Ws       = (const float*)d_in[5];
    const float* Kv       = (const float*)d_in[6];
    const float* w0       = (const float*)d_in[7];
    const float* b0       = (const float*)d_in[8];
    const float* KP       = (const float*)d_in[9];
    float* out = (float*)d_out;

    const int n    = in_sizes[0] / 3;
    const int mb   = (n + 127) / 128;
    const int mb32 = (n + 31) / 32;

    float  *pdkp;
    __half *pxh, *pwfh, *pyh, *pwth, *pfth;
    cudaGetSymbolAddress((void**)&pxh,  g_xh);
    cudaGetSymbolAddress((void**)&pwfh, g_wfh);
    cudaGetSymbolAddress((void**)&pdkp, g_dkp);
    cudaGetSymbolAddress((void**)&pyh,  g_yh);
    cudaGetSymbolAddress((void**)&pwth, g_wth);
    cudaGetSymbolAddress((void**)&pfth, g_feath);

    const int SM_128 = 2 * (128 + 128) * 72 * 2;  // 73728 (shortcut/conv3)
    const int SM_CV2 = 2 * (32 + 128)  * 72 * 2;  // 46080
    const int SM_F0  = 2 * (32 + 64)   * 72 * 2;  // 27648
    cudaFuncSetAttribute(mma_gemm_f16<128,128,0>, cudaFuncAttributeMaxDynamicSharedMemorySize, SM_128);
    cudaFuncSetAttribute(mma_gemm_f16<128,128,1>, cudaFuncAttributeMaxDynamicSharedMemorySize, SM_128);
    cudaFuncSetAttribute(mma_gemm_f16<32,128,3>,  cudaFuncAttributeMaxDynamicSharedMemorySize, SM_CV2);
    cudaFuncSetAttribute(mma_gemm_f16<32,64,2>,   cudaFuncAttributeMaxDynamicSharedMemorySize, SM_F0);

    // 0. merged prep
    const int prep_total = n * INF + PREP_EXTRA;
    prep_kernel<<<(prep_total + 255) / 256, 256>>>(features, Ws, W3, Kv, w0,
                                                   pfth, pwth, n * INF);

    // 1. conv1 (exact fp32): x = lrelu(features @ W1) -> fp16 [n,128]
    fp32_gemm<<<dim3(1, mb), 256>>>(features, W1, pxh, n, MID, INF);
    // 2. rigid wf (fp16, [c][k16])                       [n,2048]
    wf_kernel<<<(n + 3) / 4, 256>>>(points, nbr, pxh, KP, nullptr, pwfh, n);
    // 3. f0 -> deformed kernel points                    [n,45]  (BM=32)
    mma_gemm_f16<32,64,2><<<dim3(1, mb32), 256, SM_F0>>>(pwfh, pwth + OFF_W0TH, pdkp,
                                                         b0, KP, n, KWF, 0);
    // 4. deformed wf2                                    [n,2048]
    wf_kernel<<<(n + 3) / 4, 256>>>(points, nbr, pxh, KP, pdkp, pwfh, n);
    // 5. conv2: y = lrelu(wf2 @ Kv) -> fp16              [n,128] (BM=32)
    mma_gemm_f16<32,128,3><<<dim3(1, mb32), 256, SM_CV2>>>(pwfh, pwth + OFF_KVTH, pyh,
                                                           nullptr, nullptr, n, KWF, MID);
    // 6. shortcut: out = lrelu(feat @ Ws)                [n,512]
    mma_gemm_f16<128,128,0><<<dim3(4, mb), 256, SM_128>>>(pfth, pwth + OFF_WSTH, out,
                                                          nullptr, nullptr, n, INF, OUTF);
    // 7. out = lrelu(lrelu(y @ W3) + out)                [n,512]
    mma_gemm_f16<128,128,1><<<dim3(4, mb), 256, SM_128>>>(pyh, pwth + OFF_W3TH, out,
                                                          nullptr, nullptr, n, MID, OUTF);
}

// round 16
// speedup vs baseline: 1.1946x; 1.1946x over previous
#include <cuda_runtime.h>
#include <cuda_fp16.h>
#include <cstddef>
#include <cstdint>

// ---------------- problem constants ----------------
#define MAXN   20000
#define NN     32
#define INF    256
#define MID    128
#define OUTF   512
#define NKP    15
#define EXTENT 0.5f
#define INV_EXTENT 2.0f

// ---------------- scratch (allocation-free) ----------------
__device__ __half g_xh  [(size_t)MAXN * MID];      // conv1 output (fp16)
__device__ __half g_wfh [(size_t)MAXN * NKP*MID];  // wf / wf2 (fp16)
__device__ float  g_dkp [(size_t)MAXN * NKP*3];    // deformed KPs (fp32)
__device__ __half g_yh  [(size_t)MAXN * MID];      // conv2 output (fp16)
__device__ __half g_feath[(size_t)MAXN * INF];     // features (fp16)
// fp16 K-major weights: Wst | W3t | Kvt | w0t(pad64)
#define OFF_WSTH 0
#define OFF_W3TH (OFF_WSTH + 512*256)
#define OFF_KVTH (OFF_W3TH + 512*128)
#define OFF_W0TH (OFF_KVTH + 128*1920)
#define WTH_TOTAL (OFF_W0TH + 64*1920)
__device__ __half g_wth[WTH_TOTAL];

__device__ __forceinline__ float lrelu(float x) { return fmaxf(x, 0.1f * x); }
__device__ __forceinline__ void fma2(float2 &d, float2 a, float2 b) {
    asm("fma.rn.f32x2 %0, %1, %2, %0;"
        : "+l"(reinterpret_cast<unsigned long long&>(d))
        : "l"(reinterpret_cast<unsigned long long&>(a)),
          "l"(reinterpret_cast<unsigned long long&>(b)));
}
__device__ __forceinline__ uint32_t smem_u32(const void* p) {
    uint32_t a;
    asm("{ .reg .u64 t; cvta.to.shared.u64 t, %1; cvt.u32.u64 %0, t; }" : "=r"(a) : "l"(p));
    return a;
}
__device__ __forceinline__ void cpasync16(uint32_t dst, const void* src, bool pred) {
    int sz = pred ? 16 : 0;
    asm volatile("cp.async.cg.shared.global [%0], [%1], 16, %2;"
                 :: "r"(dst), "l"(src), "r"(sz));
}
#define CP_COMMIT() asm volatile("cp.async.commit_group;")
#define CP_WAIT(n)  asm volatile("cp.async.wait_group %0;" :: "n"(n))

__device__ __forceinline__ void mma_f16(float* d, const uint32_t* a, const uint32_t* b) {
    asm volatile(
        "mma.sync.aligned.m16n8k16.row.col.f32.f16.f16.f32 "
        "{%0,%1,%2,%3}, {%4,%5,%6,%7}, {%8,%9}, {%0,%1,%2,%3};"
        : "+f"(d[0]), "+f"(d[1]), "+f"(d[2]), "+f"(d[3])
        : "r"(a[0]), "r"(a[1]), "r"(a[2]), "r"(a[3]), "r"(b[0]), "r"(b[1]));
}

// =====================================================================
// Merged prep: features->fp16 + 4 fp16 weight transposes. One launch.
// =====================================================================
__global__ void prep_kernel(const float* __restrict__ feat,
                            const float* __restrict__ Ws, const float* __restrict__ W3,
                            const float* __restrict__ Kv, const float* __restrict__ w0,
                            __half* __restrict__ pfth, __half* __restrict__ pwth, int nfeat)
{
    int idx = blockIdx.x * 256 + threadIdx.x;
    if (idx < nfeat) { pfth[idx] = __float2half_rn(feat[idx]); return; }
    idx -= nfeat;
    if (idx < 512 * 256) {                      // Wst [512,256] <- Ws[256,512]
        int nr = idx >> 8, k = idx & 255;
        pwth[OFF_WSTH + idx] = __float2half_rn(Ws[(size_t)k * 512 + nr]);
        return;
    }
    idx -= 512 * 256;
    if (idx < 512 * 128) {                      // W3t [512,128] <- W3[128,512]
        int nr = idx >> 7, k = idx & 127;
        pwth[OFF_W3TH + idx] = __float2half_rn(W3[(size_t)k * 512 + nr]);
        return;
    }
    idx -= 512 * 128;
    if (idx < 128 * 1920) {                     // Kvt [128,1920] <- Kv[1920,128]
        int nr = idx / 1920, k = idx - nr * 1920;
        pwth[OFF_KVTH + idx] = __float2half_rn(Kv[(size_t)k * 128 + nr]);
        return;
    }
    idx -= 128 * 1920;
    if (idx < 64 * 1920) {                      // w0t [64,1920] <- w0[1920,45] pad
        int nr = idx / 1920, k = idx - nr * 1920;
        pwth[OFF_W0TH + idx] = (nr < 45) ? __float2half_rn(w0[(size_t)k * 45 + nr])
                                         : __float2half_rn(0.0f);
    }
}
#define PREP_EXTRA (512*256 + 512*128 + 128*1920 + 64*1920)

// =====================================================================
// Exact fp32 SGEMM (f32x2): C(half) = lrelu(A @ B). Used for conv1.
// =====================================================================
__global__ __launch_bounds__(256)
void fp32_gemm(const float* __restrict__ A, const float* __restrict__ B,
               __half* __restrict__ C, int M, int N, int K)
{
    constexpr int BM = 128, BN = 128, BK = 16;
    __shared__ float As[BK][BM];
    __shared__ float Bs[BK][BN];

    const int tid  = threadIdx.x;
    const int bm   = blockIdx.y * BM;
    const int bn   = blockIdx.x * BN;
    const int trow = (tid / 16) * 8;
    const int tcol = (tid % 16) * 8;

    float2 acc[8][4];
#pragma unroll
    for (int m = 0; m < 8; m++)
#pragma unroll
        for (int j = 0; j < 4; j++) acc[m][j] = make_float2(0.f, 0.f);

    for (int k0 = 0; k0 < K; k0 += BK) {
#pragma unroll
        for (int i = 0; i < 2; i++) {
            int idx = tid + i * 256;
            int r = idx >> 2;
            int c = (idx & 3) << 2;
            float4 v = make_float4(0.f, 0.f, 0.f, 0.f);
            if (bm + r < M)
                v = *(const float4*)(A + (size_t)(bm + r) * K + k0 + c);
            As[c + 0][r] = v.x; As[c + 1][r] = v.y;
            As[c + 2][r] = v.z; As[c + 3][r] = v.w;
        }
#pragma unroll
        for (int i = 0; i < 2; i++) {
            int idx = tid + i * 256;
            int r = idx >> 5;
            int c = (idx & 31) << 2;
            *(float4*)&Bs[r][c] = *(const float4*)(B + (size_t)(k0 + r) * N + bn + c);
        }
        __syncthreads();

#pragma unroll
        for (int kk = 0; kk < BK; kk++) {
            float a[8];
            float2 b[4];
            {
                float4 t0 = *(const float4*)&As[kk][trow];
                float4 t1 = *(const float4*)&As[kk][trow + 4];
                a[0]=t0.x; a[1]=t0.y; a[2]=t0.z; a[3]=t0.w;
                a[4]=t1.x; a[5]=t1.y; a[6]=t1.z; a[7]=t1.w;
            }
#pragma unroll
            for (int j = 0; j < 4; j++) b[j] = *(const float2*)&Bs[kk][tcol + 2 * j];
#pragma unroll
            for (int m = 0; m < 8; m++) {
                float2 am = make_float2(a[m], a[m]);
#pragma unroll
                for (int j = 0; j < 4; j++) fma2(acc[m][j], am, b[j]);
            }
        }
        __syncthreads();
    }

#pragma unroll
    for (int m = 0; m < 8; m++) {
        int row = bm + trow + m;
        if (row >= M) continue;
        __half2 h[4];
#pragma unroll
        for (int j = 0; j < 4; j++)
            h[j] = __floats2half2_rn(lrelu(acc[m][j].x), lrelu(acc[m][j].y));
        *(uint2*)(C + (size_t)row * N + bn + tcol) =
            make_uint2(*(uint32_t*)&h[0], *(uint32_t*)&h[1]);
        *(uint2*)(C + (size_t)row * N + bn + tcol + 4) =
            make_uint2(*(uint32_t*)&h[2], *(uint32_t*)&h[3]);
    }
}

// =====================================================================
// FP16 mma.sync GEMM (m16n8k16, fp32 accumulate). BK=64 halves.
// MODE 2: dkp[i,o<45] = KP[o] + (acc+b0[o])*EXTENT (f0)
// MODE 3: Ch = half(lrelu(acc))                    (conv2 -> y fp16)
// =====================================================================
template<int BM, int BN, int MODE>
__global__ __launch_bounds__(256)
void mma_gemm_f16(const __half* __restrict__ A, const __half* __restrict__ Bt,
                  void* __restrict__ Cv, const float* __restrict__ b0,
                  const float* __restrict__ KP, int M, int K, int Nf)
{
    constexpr int BK = 64;
    constexpr int NW = (BN == 128) ? 4 : 2;
    constexpr int MW = 8 / NW;
    constexpr int WM = BM / MW;
    constexpr int WN = BN / NW;
    constexpr int AM = WM / 16;
    constexpr int AN = WN / 8;
    constexpr int LDS_PAD = 72;
    constexpr int ASZ = BM * LDS_PAD;
    constexpr int BSZ = BN * LDS_PAD;
    constexpr int CPR = BK / 8;

    extern __shared__ __align__(16) __half smh[];
    __half* As = smh;
    __half* Bs = smh + 2 * ASZ;
    const uint32_t sA = smem_u32(As);
    const uint32_t sB = smem_u32(Bs);

    const int tid  = threadIdx.x;
    const int lane = tid & 31;
    const int g    = lane >> 2;
    const int tig  = lane & 3;
    const int warp = tid >> 5;
    const int wm   = warp / NW;
    const int wn   = warp % NW;
    const int bm   = blockIdx.y * BM;
    const int bn   = blockIdx.x * BN;

    float acc[AM][AN][4];
#pragma unroll
    for (int i = 0; i < AM; i++)
#pragma unroll
        for (int j = 0; j < AN; j++)
#pragma unroll
            for (int e = 0; e < 4; e++) acc[i][j][e] = 0.f;

    const int NT = K / BK;

    auto load_tile = [&](int it, int buf) {
        const int k0 = it * BK;
#pragma unroll
        for (int i = 0; i < BM * CPR / 256; i++) {
            int idx = tid + i * 256;
            int r = idx / CPR, c8 = (idx % CPR) << 3;
            bool p = (bm + r) < M;
            const __half* src = A + (size_t)(p ? bm + r : 0) * K + k0 + c8;
            cpasync16(sA + (buf * ASZ + r * LDS_PAD + c8) * 2, src, p);
        }
#pragma unroll
        for (int i = 0; i < BN * CPR / 256; i++) {
            int idx = tid + i * 256;
            int r = idx / CPR, c8 = (idx % CPR) << 3;
            const __half* src = Bt + (size_t)(bn + r) * K + k0 + c8;
            cpasync16(sB + (buf * BSZ + r * LDS_PAD + c8) * 2, src, true);
        }
        CP_COMMIT();
    };

    load_tile(0, 0);
    for (int it = 0; it < NT; it++) {
        const int cur = it & 1;
        if (it + 1 < NT) { load_tile(it + 1, cur ^ 1); CP_WAIT(1); }
        else             { CP_WAIT(0); }
        __syncthreads();

        const __half* Ab = As + cur * ASZ;
        const __half* Bb = Bs + cur * BSZ;
#pragma unroll
        for (int ks = 0; ks < BK / 16; ks++) {
            const int kb = ks * 16 + 2 * tig;
            uint32_t af[AM][4], bf[AN][2];
#pragma unroll
            for (int am = 0; am < AM; am++) {
                int r0 = wm * WM + am * 16 + g;
                af[am][0] = *(const uint32_t*)&Ab[r0 * LDS_PAD + kb];
                af[am][1] = *(const uint32_t*)&Ab[(r0 + 8) * LDS_PAD + kb];
                af[am][2] = *(const uint32_t*)&Ab[r0 * LDS_PAD + kb + 8];
                af[am][3] = *(const uint32_t*)&Ab[(r0 + 8) * LDS_PAD + kb + 8];
            }
#pragma unroll
            for (int an = 0; an < AN; an++) {
                int c0 = wn * WN + an * 8 + g;
                bf[an][0] = *(const uint32_t*)&Bb[c0 * LDS_PAD + kb];
                bf[an][1] = *(const uint32_t*)&Bb[c0 * LDS_PAD + kb + 8];
            }
#pragma unroll
            for (int am = 0; am < AM; am++)
#pragma unroll
                for (int an = 0; an < AN; an++)
                    mma_f16(acc[am][an], af[am], bf[an]);
        }
        __syncthreads();
    }

    float*  Cf = (float*)Cv;
    __half* Ch = (__half*)Cv;
#pragma unroll
    for (int am = 0; am < AM; am++) {
        const int r0 = bm + wm * WM + am * 16 + g;
#pragma unroll
        for (int an = 0; an < AN; an++) {
            const int c = bn + wn * WN + an * 8 + tig * 2;
#pragma unroll
            for (int half_ = 0; half_ < 2; half_++) {
                int row = r0 + half_ * 8;
                if (row >= M) continue;
                float d0 = acc[am][an][half_ * 2 + 0];
                float d1 = acc[am][an][half_ * 2 + 1];
                if (MODE == 2) {
                    float* dp = Cf + (size_t)row * (NKP * 3);
                    if (c < NKP * 3)     dp[c]     = KP[c]     + (d0 + b0[c])     * EXTENT;
                    if (c + 1 < NKP * 3) dp[c + 1] = KP[c + 1] + (d1 + b0[c + 1]) * EXTENT;
                } else {
                    *(__half2*)(Ch + (size_t)row * Nf + c) =
                        __floats2half2_rn(lrelu(d0), lrelu(d1));
                }
            }
        }
    }
}

// =====================================================================
// FUSED shortcut + conv3:
//   s   = lrelu(feat @ Ws)       (K1 = 256)
//   out = lrelu(lrelu(y @ W3) + s)  (K2 = 128)
// BM=BN=128, 8 warps (2x4), AM=2, AN=4. Two sequential mainloops over
// the same smem double buffer; s kept in 32 registers. Saves the full
// out round-trip (82 MB).
// =====================================================================
__global__ __launch_bounds__(256)
void fused_out_kernel(const __half* __restrict__ Af, const __half* __restrict__ Ay,
                      const __half* __restrict__ Bws, const __half* __restrict__ Bw3,
                      float* __restrict__ C, int M)
{
    constexpr int BM = 128, BN = 128, BK = 64;
    constexpr int NW = 4, WM = 64, WN = 32, AM = 4, AN = 4;  // MW=2
    constexpr int LDS_PAD = 72;
    constexpr int ASZ = BM * LDS_PAD;
    constexpr int BSZ = BN * LDS_PAD;
    constexpr int CPR = BK / 8;

    extern __shared__ __align__(16) __half smh[];
    __half* As = smh;
    __half* Bs = smh + 2 * ASZ;
    const uint32_t sA = smem_u32(As);
    const uint32_t sB = smem_u32(Bs);

    const int tid  = threadIdx.x;
    const int lane = tid & 31;
    const int g    = lane >> 2;
    const int tig  = lane & 3;
    const int warp = tid >> 5;
    const int wm   = warp / NW;
    const int wn   = warp % NW;
    const int bm   = blockIdx.y * BM;
    const int bn   = blockIdx.x * BN;

    float acc[AM][AN][4];
    float sres[AM][AN][4];

    auto run_phase = [&](const __half* A, const __half* Bt, int K) {
#pragma unroll
        for (int i = 0; i < AM; i++)
#pragma unroll
            for (int j = 0; j < AN; j++)
#pragma unroll
                for (int e = 0; e < 4; e++) acc[i][j][e] = 0.f;

        const int NT = K / BK;
        auto load_tile = [&](int it, int buf) {
            const int k0 = it * BK;
#pragma unroll
            for (int i = 0; i < BM * CPR / 256; i++) {
                int idx = tid + i * 256;
                int r = idx / CPR, c8 = (idx % CPR) << 3;
                bool p = (bm + r) < M;
                const __half* src = A + (size_t)(p ? bm + r : 0) * K + k0 + c8;
                cpasync16(sA + (buf * ASZ + r * LDS_PAD + c8) * 2, src, p);
            }
#pragma unroll
            for (int i = 0; i < BN * CPR / 256; i++) {
                int idx = tid + i * 256;
                int r = idx / CPR, c8 = (idx % CPR) << 3;
                const __half* src = Bt + (size_t)(bn + r) * K + k0 + c8;
                cpasync16(sB + (buf * BSZ + r * LDS_PAD + c8) * 2, src, true);
            }
            CP_COMMIT();
        };

        load_tile(0, 0);
        for (int it = 0; it < NT; it++) {
            const int cur = it & 1;
            if (it + 1 < NT) { load_tile(it + 1, cur ^ 1); CP_WAIT(1); }
            else             { CP_WAIT(0); }
            __syncthreads();

            const __half* Ab = As + cur * ASZ;
            const __half* Bb = Bs + cur * BSZ;
#pragma unroll
            for (int ks = 0; ks < BK / 16; ks++) {
                const int kb = ks * 16 + 2 * tig;
                uint32_t af[AM][4], bf[AN][2];
#pragma unroll
                for (int am = 0; am < AM; am++) {
                    int r0 = wm * WM + am * 16 + g;
                    af[am][0] = *(const uint32_t*)&Ab[r0 * LDS_PAD + kb];
                    af[am][1] = *(const uint32_t*)&Ab[(r0 + 8) * LDS_PAD + kb];
                    af[am][2] = *(const uint32_t*)&Ab[r0 * LDS_PAD + kb + 8];
                    af[am][3] = *(const uint32_t*)&Ab[(r0 + 8) * LDS_PAD + kb + 8];
                }
#pragma unroll
                for (int an = 0; an < AN; an++) {
                    int c0 = wn * WN + an * 8 + g;
                    bf[an][0] = *(const uint32_t*)&Bb[c0 * LDS_PAD + kb];
                    bf[an][1] = *(const uint32_t*)&Bb[c0 * LDS_PAD + kb + 8];
                }
#pragma unroll
                for (int am = 0; am < AM; am++)
#pragma unroll
                    for (int an = 0; an < AN; an++)
                        mma_f16(acc[am][an], af[am], bf[an]);
            }
            __syncthreads();
        }
    };

    // phase 1: shortcut s = lrelu(feat @ Ws), K=256
    run_phase(Af, Bws, INF);
#pragma unroll
    for (int i = 0; i < AM; i++)
#pragma unroll
        for (int j = 0; j < AN; j++)
#pragma unroll
            for (int e = 0; e < 4; e++) sres[i][j][e] = lrelu(acc[i][j][e]);

    // phase 2: conv3 acc = y @ W3, K=128
    run_phase(Ay, Bw3, MID);

    // epilogue: out = lrelu(lrelu(acc) + s)
#pragma unroll
    for (int am = 0; am < AM; am++) {
        const int r0 = bm + wm * 64 + am * 16 + g;
#pragma unroll
        for (int an = 0; an < AN; an++) {
            const int c = bn + wn * 32 + an * 8 + tig * 2;
#pragma unroll
            for (int half_ = 0; half_ < 2; half_++) {
                int row = r0 + half_ * 8;
                if (row >= M) continue;
                float d0 = lrelu(lrelu(acc[am][an][half_ * 2 + 0]) + sres[am][an][half_ * 2 + 0]);
                float d1 = lrelu(lrelu(acc[am][an][half_ * 2 + 1]) + sres[am][an][half_ * 2 + 1]);
                *(float2*)(C + (size_t)row * OUTF + c) = make_float2(d0, d1);
            }
        }
    }
}

// =====================================================================
// Per-point gather + KP-influence + weighted feature aggregation.
// 4 points per block, 256 threads, warp-uniform neighbor compaction.
// =====================================================================
__global__ __launch_bounds__(256)
void wf_kernel(const float* __restrict__ points, const int* __restrict__ nbr,
               const __half* __restrict__ xf, const float* __restrict__ kp0,
               const float* __restrict__ dkp, __half* __restrict__ wf, int n)
{
    const int tid = threadIdx.x;
    const int i0  = blockIdx.x * 4;

    __shared__ int   s_idx[4][NN];
    __shared__ float s_w[4][NN][16];
    __shared__ int   s_cnt[4];
    __shared__ float s_ctr[4][3];

    if (tid < 12) {
        int pt = tid / 3, d = tid - pt * 3;
        int ip = i0 + pt;
        s_ctr[pt][d] = (ip < n) ? points[(size_t)ip * 3 + d] : 0.f;
    }
    __syncthreads();

    if (tid < 128) {
        const int pt = tid >> 5, j = tid & 31;
        const int ip = i0 + pt;
        int   id = 0;
        float wreg[NKP];
        bool  active = false;
        if (ip < n) {
            id = nbr[(size_t)ip * NN + j];
            float dx = points[(size_t)id * 3 + 0] - s_ctr[pt][0];
            float dy = points[(size_t)id * 3 + 1] - s_ctr[pt][1];
            float dz = points[(size_t)id * 3 + 2] - s_ctr[pt][2];
            const float* kp = dkp ? (dkp + (size_t)ip * (NKP * 3)) : kp0;
#pragma unroll
            for (int k = 0; k < NKP; k++) {
                float ex = dx - kp[k * 3 + 0];
                float ey = dy - kp[k * 3 + 1];
                float ez = dz - kp[k * 3 + 2];
                float d = sqrtf(ex * ex + ey * ey + ez * ez);
                float w = fmaxf(1.0f - d * INV_EXTENT, 0.0f);
                wreg[k] = w;
                active |= (w > 0.0f);
            }
        }
        unsigned mask = __ballot_sync(0xFFFFFFFFu, active);
        if (active) {
            int pos = __popc(mask & ((1u << j) - 1u));
            s_idx[pt][pos] = id;
#pragma unroll
            for (int k = 0; k < NKP; k++) s_w[pt][pos][k] = wreg[k];
            s_w[pt][pos][15] = 0.0f;
        }
        if (j == 0) s_cnt[pt] = __popc(mask);
    }
    __syncthreads();

    const int p  = tid >> 6;
    const int t2 = (tid & 63) << 1;
    const int i  = i0 + p;
    if (i >= n) return;
    const int cnt = s_cnt[p];

    float2 acc[NKP];
#pragma unroll
    for (int k = 0; k < NKP; k++) acc[k] = make_float2(0.f, 0.f);

#pragma unroll 4
    for (int m = 0; m < cnt; m++) {
        int id = s_idx[p][m];
        float2 f = __half22float2(*(const __half2*)(xf + (size_t)id * MID + t2));
        float4 w0_ = *(const float4*)&s_w[p][m][0];
        float4 w1_ = *(const float4*)&s_w[p][m][4];
        float4 w2_ = *(const float4*)&s_w[p][m][8];
        float4 w3_ = *(const float4*)&s_w[p][m][12];
        fma2(acc[0],  make_float2(w0_.x, w0_.x), f);
        fma2(acc[1],  make_float2(w0_.y, w0_.y), f);
        fma2(acc[2],  make_float2(w0_.z, w0_.z), f);
        fma2(acc[3],  make_float2(w0_.w, w0_.w), f);
        fma2(acc[4],  make_float2(w1_.x, w1_.x), f);
        fma2(acc[5],  make_float2(w1_.y, w1_.y), f);
        fma2(acc[6],  make_float2(w1_.z, w1_.z), f);
        fma2(acc[7],  make_float2(w1_.w, w1_.w), f);
        fma2(acc[8],  make_float2(w2_.x, w2_.x), f);
        fma2(acc[9],  make_float2(w2_.y, w2_.y), f);
        fma2(acc[10], make_float2(w2_.z, w2_.z), f);
        fma2(acc[11], make_float2(w2_.w, w2_.w), f);
        fma2(acc[12], make_float2(w3_.x, w3_.x), f);
        fma2(acc[13], make_float2(w3_.y, w3_.y), f);
        fma2(acc[14], make_float2(w3_.z, w3_.z), f);
    }

    size_t base = (size_t)i * (NKP * MID) + t2;
#pragma unroll
    for (int k = 0; k < NKP; k++)
        *(__half2*)(wf + base + (size_t)k * MID) =
            __floats2half2_rn(acc[k].x, acc[k].y);
}

// =====================================================================
extern "C" void kernel_launch(void* const* d_in, const int* in_sizes, int n_in,
                              void* d_out, int out_size)
{
    const float* points   = (const float*)d_in[0];
    const float* features = (const float*)d_in[1];
    const int*   nbr      = (const int*)  d_in[2];
    const float* W1       = (const float*)d_in[3];
    const float* W3       = (const float*)d_in[4];
    const float* Ws       = (const float*)d_in[5];
    const float* Kv       = (const float*)d_in[6];
    const float* w0       = (const float*)d_in[7];
    const float* b0       = (const float*)d_in[8];
    const float* KP       = (const float*)d_in[9];
    float* out = (float*)d_out;

    const int n    = in_sizes[0] / 3;
    const int mb   = (n + 127) / 128;
    const int mb64 = (n + 63) / 64;

    float  *pdkp;
    __half *pxh, *pwfh, *pyh, *pwth, *pfth;
    cudaGetSymbolAddress((void**)&pxh,  g_xh);
    cudaGetSymbolAddress((void**)&pwfh, g_wfh);
    cudaGetSymbolAddress((void**)&pdkp, g_dkp);
    cudaGetSymbolAddress((void**)&pyh,  g_yh);
    cudaGetSymbolAddress((void**)&pwth, g_wth);
    cudaGetSymbolAddress((void**)&pfth, g_feath);

    const int SM_FUSED = 2 * (128 + 128) * 72 * 2;  // 73728
    const int SM_CV2   = 2 * (64 + 128)  * 72 * 2;  // 55296
    const int SM_F0    = 2 * (64 + 64)   * 72 * 2;  // 36864
    cudaFuncSetAttribute(fused_out_kernel,        cudaFuncAttributeMaxDynamicSharedMemorySize, SM_FUSED);
    cudaFuncSetAttribute(mma_gemm_f16<64,128,3>,  cudaFuncAttributeMaxDynamicSharedMemorySize, SM_CV2);
    cudaFuncSetAttribute(mma_gemm_f16<64,64,2>,   cudaFuncAttributeMaxDynamicSharedMemorySize, SM_F0);

    // 0. merged prep: features->fp16 + fp16 weight transposes
    const int prep_total = n * INF + PREP_EXTRA;
    prep_kernel<<<(prep_total + 255) / 256, 256>>>(features, Ws, W3, Kv, w0,
                                                   pfth, pwth, n * INF);

    // 1. conv1 (exact fp32 compute): x = lrelu(features @ W1) -> fp16 [n,128]
    fp32_gemm<<<dim3(1, mb), 256>>>(features, W1, pxh, n, MID, INF);
    // 2. rigid influence-weighted features wf (fp16)    [n,1920]
    wf_kernel<<<(n + 3) / 4, 256>>>(points, nbr, pxh, KP, nullptr, pwfh, n);
    // 3. f0 = wf @ w0 + b0 -> deformed kernel points    [n,45]
    mma_gemm_f16<64,64,2><<<dim3(1, mb64), 256, SM_F0>>>(pwfh, pwth + OFF_W0TH, pdkp,
                                                         b0, KP, n, NKP * MID, 0);
    // 4. deformed influence-weighted features wf2       [n,1920]
    wf_kernel<<<(n + 3) / 4, 256>>>(points, nbr, pxh, KP, pdkp, pwfh, n);
    // 5. conv2: y = lrelu(wf2 @ Kv) -> fp16             [n,128]
    mma_gemm_f16<64,128,3><<<dim3(1, mb64), 256, SM_CV2>>>(pwfh, pwth + OFF_KVTH, pyh,
                                                           nullptr, nullptr, n, NKP * MID, MID);
    // 6+7 fused: out = lrelu(lrelu(y@W3) + lrelu(feat@Ws))  [n,512]
    fused_out_kernel<<<dim3(4, mb), 256, SM_FUSED>>>(pfth, pyh,
                                                     pwth + OFF_WSTH, pwth + OFF_W3TH,
                                                     out, n);
}